// round 1
// baseline (speedup 1.0000x reference)
#include <cuda_runtime.h>
#include <math.h>

#define B_  4096
#define E_  64
#define D_  1024
#define BM  32
#define KC  32
#define NC  64
#define NBLK (B_ / BM)   // 128

// Scratch (allocation-free rule: __device__ globals)
__device__ float g_sinv[D_];
__device__ float g_es[E_ * D_];   // sigma_inv * expert_keys
__device__ float g_en[E_];        // sum_d sigma_inv * ek^2

// ---------------------------------------------------------------------------
// Prep: sigma_inv, scaled experts, expert norms. Tiny (64 blocks).
// ---------------------------------------------------------------------------
__global__ __launch_bounds__(256) void prep_kernel(const float* __restrict__ ek,
                                                   const float* __restrict__ ls) {
    int e = blockIdx.x;
    int tid = threadIdx.x;
    float acc = 0.f;
    for (int d = tid; d < D_; d += 256) {
        float s = __expf(-ls[d]);
        if (e == 0) g_sinv[d] = s;
        float v = ek[e * D_ + d];
        float sv = s * v;
        g_es[e * D_ + d] = sv;
        acc += sv * v;
    }
    __shared__ float red[8];
    #pragma unroll
    for (int o = 16; o > 0; o >>= 1) acc += __shfl_down_sync(0xffffffffu, acc, o);
    if ((tid & 31) == 0) red[tid >> 5] = acc;
    __syncthreads();
    if (tid == 0) {
        float s = 0.f;
        #pragma unroll
        for (int i = 0; i < 8; i++) s += red[i];
        g_en[e] = s;
    }
}

// ---------------------------------------------------------------------------
// Fused main kernel: dist GEMM -> similarity -> softmax -> weights@ek GEMM
// 128 blocks x 256 threads, BM=32 rows per block.
// ---------------------------------------------------------------------------
__global__ __launch_bounds__(256) void MahalanobisSimilarity_71502615544487_kernel(
        const float* __restrict__ z,
        const float* __restrict__ ek,
        float* __restrict__ out_sim,   // [B, E]
        float* __restrict__ out_w)     // [B, D]
{
    __shared__ float sZ[BM][KC + 4];    // z tile, 32x36
    __shared__ float sE[E_][KC + 4];    // es tile, 64x36
    __shared__ float sW[BM][E_ + 4];    // similarity -> weights, 32x68
    __shared__ float sB[E_][NC + 4];    // ek tile for phase 3, 64x68
    __shared__ float s_zn[BM];
    __shared__ float s_en[E_];

    const int tid = threadIdx.x;
    const int r0  = blockIdx.x * BM;
    const int tx  = tid & 15;
    const int ty  = tid >> 4;

    if (tid < E_) s_en[tid] = g_en[tid];

    // ---- Phase 0: zn[m] = sum_d sinv * z^2 (8 threads per row) ----
    {
        int row = tid >> 3;
        int l8  = tid & 7;
        const float* zr = z + (size_t)(r0 + row) * D_;
        float acc = 0.f;
        for (int k = l8 * 4; k < D_; k += 32) {
            float4 v = *(const float4*)(zr + k);
            float4 s = *(const float4*)(g_sinv + k);
            acc += s.x * v.x * v.x + s.y * v.y * v.y
                 + s.z * v.z * v.z + s.w * v.w * v.w;
        }
        acc += __shfl_down_sync(0xffffffffu, acc, 4, 8);
        acc += __shfl_down_sync(0xffffffffu, acc, 2, 8);
        acc += __shfl_down_sync(0xffffffffu, acc, 1, 8);
        if (l8 == 0) s_zn[row] = acc;
    }

    // ---- Phase 1: dot[m][e] = z_m . es_e  (M=32, N=64, K=1024 tiled GEMM) ----
    float acc[2][4];
    #pragma unroll
    for (int i = 0; i < 2; i++)
        #pragma unroll
        for (int j = 0; j < 4; j++) acc[i][j] = 0.f;

    for (int kc = 0; kc < D_; kc += KC) {
        __syncthreads();
        {   // sZ: 32x32, one float4 per thread
            int m  = tid >> 3;
            int k4 = (tid & 7) << 2;
            float4 v = *(const float4*)(z + (size_t)(r0 + m) * D_ + kc + k4);
            *(float4*)(&sZ[m][k4]) = v;
        }
        #pragma unroll
        for (int i = 0; i < 2; i++) {   // sE: 64x32, two float4 per thread
            int e  = (tid >> 3) + 32 * i;
            int k4 = (tid & 7) << 2;
            float4 v = *(const float4*)(g_es + (size_t)e * D_ + kc + k4);
            *(float4*)(&sE[e][k4]) = v;
        }
        __syncthreads();
        #pragma unroll
        for (int k = 0; k < KC; k++) {
            float a0 = sZ[ty][k];
            float a1 = sZ[ty + 16][k];
            #pragma unroll
            for (int j = 0; j < 4; j++) {
                float b = sE[tx + 16 * j][k];
                acc[0][j] = fmaf(a0, b, acc[0][j]);
                acc[1][j] = fmaf(a1, b, acc[1][j]);
            }
        }
    }
    __syncthreads();

    // ---- Phase 2a: similarity = 1/(1+dist), write out + stage in smem ----
    #pragma unroll
    for (int i = 0; i < 2; i++) {
        int m = ty + 16 * i;
        float zn = s_zn[m];
        #pragma unroll
        for (int j = 0; j < 4; j++) {
            int e = tx + 16 * j;
            float dist = zn + s_en[e] - 2.f * acc[i][j];
            float sim  = 1.f / (1.f + dist);
            sW[m][e] = sim;
            out_sim[(size_t)(r0 + m) * E_ + e] = sim;
        }
    }
    __syncthreads();

    // ---- Phase 2b: softmax over E per row (1 warp handles 4 rows) ----
    {
        int w = tid >> 5, lane = tid & 31;
        #pragma unroll
        for (int rr = 0; rr < 4; rr++) {
            int m = w * 4 + rr;
            float v0 = sW[m][lane];
            float v1 = sW[m][lane + 32];
            float mx = fmaxf(v0, v1);
            #pragma unroll
            for (int o = 16; o; o >>= 1)
                mx = fmaxf(mx, __shfl_xor_sync(0xffffffffu, mx, o));
            float e0 = __expf(v0 - mx);
            float e1 = __expf(v1 - mx);
            float s = e0 + e1;
            #pragma unroll
            for (int o = 16; o; o >>= 1)
                s += __shfl_xor_sync(0xffffffffu, s, o);
            float inv = 1.f / s;
            sW[m][lane]      = e0 * inv;
            sW[m][lane + 32] = e1 * inv;
        }
    }
    __syncthreads();

    // ---- Phase 3: out_w[m][d] = sum_e W[m][e] * ek[e][d]  (chunks of NC) ----
    for (int dc = 0; dc < D_; dc += NC) {
        #pragma unroll
        for (int i = 0; i < 4; i++) {   // sB: 64x64, four float4 per thread
            int e = (tid >> 4) + 16 * i;
            int n = (tid & 15) << 2;
            float4 v = *(const float4*)(ek + (size_t)e * D_ + dc + n);
            *(float4*)(&sB[e][n]) = v;
        }
        __syncthreads();
        float o0[4] = {0.f, 0.f, 0.f, 0.f};
        float o1[4] = {0.f, 0.f, 0.f, 0.f};
        #pragma unroll
        for (int e = 0; e < E_; e++) {
            float a0 = sW[ty][e];
            float a1 = sW[ty + 16][e];
            #pragma unroll
            for (int j = 0; j < 4; j++) {
                float b = sB[e][tx + 16 * j];
                o0[j] = fmaf(a0, b, o0[j]);
                o1[j] = fmaf(a1, b, o1[j]);
            }
        }
        #pragma unroll
        for (int j = 0; j < 4; j++) {
            out_w[(size_t)(r0 + ty) * D_ + dc + tx + 16 * j]      = o0[j];
            out_w[(size_t)(r0 + ty + 16) * D_ + dc + tx + 16 * j] = o1[j];
        }
        __syncthreads();
    }
}

// ---------------------------------------------------------------------------
extern "C" void kernel_launch(void* const* d_in, const int* in_sizes, int n_in,
                              void* d_out, int out_size) {
    const float* z  = (const float*)d_in[0];   // [B, D]
    const float* ek = (const float*)d_in[1];   // [E, D]
    const float* ls = (const float*)d_in[2];   // [D]
    float* out = (float*)d_out;
    float* out_sim = out;                      // [B, E]
    float* out_w   = out + (size_t)B_ * E_;    // [B, D]

    prep_kernel<<<E_, 256>>>(ek, ls);
    MahalanobisSimilarity_71502615544487_kernel<<<NBLK, 256>>>(z, ek, out_sim, out_w);
}